// round 11
// baseline (speedup 1.0000x reference)
#include <cuda_runtime.h>
#include <cuda_fp16.h>
#include <cstdint>

#define NNODES 100000
#define NEDGES 3200000
#define NREL   8
#define CIN    128
#define HID    64
#define RELCOLS 512
#define YCOLS (RELCOLS + HID)

// ---------------- scratch ----------------------------------------------------
__device__ __align__(16) __half g_Ym[(size_t)NNODES * RELCOLS];   // relation msgs fp16
__device__ __align__(16) float  g_Yroot[(size_t)NNODES * HID];    // root part fp32
__device__ __align__(16) float  g_h[(size_t)NNODES * HID];
__device__ __align__(16) __half g_Wh1[YCOLS * CIN];
__device__ __align__(16) __half g_Wl1[YCOLS * CIN];
__device__ __align__(16) __half g_Wh2[YCOLS * HID];
__device__ __align__(16) __half g_Wl2[YCOLS * HID];
__device__ int   g_cnt[NREL * NNODES];
__device__ int   g_rowptr[NNODES + 1];
__device__ int   g_cursor[NNODES];
__device__ int   g_bsums[256];
__device__ int2  g_emeta[NEDGES];

// ---------------- CSR build --------------------------------------------------
__global__ void k_count(const int* __restrict__ dst, const int* __restrict__ et) {
    int e = blockIdx.x * blockDim.x + threadIdx.x;
    if (e < NEDGES) atomicAdd(&g_cnt[__ldcs(et + e) * NNODES + __ldcs(dst + e)], 1);
}
__global__ void k_scan1() {
    __shared__ int sh[1024];
    int d = blockIdx.x * 1024 + threadIdx.x;
    int tot = 0;
    if (d < NNODES) {
#pragma unroll
        for (int r = 0; r < NREL; r++) tot += g_cnt[r * NNODES + d];
    }
    sh[threadIdx.x] = tot;
    __syncthreads();
    for (int off = 1; off < 1024; off <<= 1) {
        int v = 0;
        if (threadIdx.x >= off) v = sh[threadIdx.x - off];
        __syncthreads();
        sh[threadIdx.x] += v;
        __syncthreads();
    }
    if (d < NNODES) g_rowptr[d] = sh[threadIdx.x] - tot;
    if (threadIdx.x == 1023) g_bsums[blockIdx.x] = sh[1023];
}
__global__ void k_scan2(int nb) {
    if (threadIdx.x == 0 && blockIdx.x == 0) {
        int run = 0;
        for (int i = 0; i < nb; i++) { int v = g_bsums[i]; g_bsums[i] = run; run += v; }
    }
}
__global__ void k_scan3() {
    int d = blockIdx.x * blockDim.x + threadIdx.x;
    if (d < NNODES) {
        int v = g_rowptr[d] + g_bsums[d >> 10];
        g_rowptr[d] = v;
        g_cursor[d] = v;
    }
    if (d == 0) g_rowptr[NNODES] = NEDGES;
}
__global__ void k_scatter(const int* __restrict__ src, const int* __restrict__ dst,
                          const int* __restrict__ et) {
    int e = blockIdx.x * blockDim.x + threadIdx.x;
    if (e >= NEDGES) return;
    int s = __ldcs(src + e), d = __ldcs(dst + e), r = __ldcs(et + e);
    int pos = atomicAdd(&g_cursor[d], 1);
    float sc = 1.0f / (float)g_cnt[r * NNODES + d];
    g_emeta[pos] = make_int2(s * RELCOLS + r * HID, __float_as_int(sc));
}

// ---------------- merged weight pack (both layers) ----------------------------
__global__ void k_pack_all(const float* __restrict__ W1, const float* __restrict__ root1,
                           const float* __restrict__ W2, const float* __restrict__ root2) {
    int i = blockIdx.x * blockDim.x + threadIdx.x;
    const int N1 = YCOLS * CIN;
    const int N2 = YCOLS * HID;
    if (i < N1) {
        int j = i / CIN, k = i % CIN;
        float v;
        if (j < RELCOLS) v = W1[(((size_t)(j >> 6)) * CIN + k) * HID + (j & 63)];
        else             v = root1[(size_t)k * HID + (j - RELCOLS)];
        __half hi = __float2half_rn(v);
        g_Wh1[i] = hi;
        g_Wl1[i] = __float2half_rn(v - __half2float(hi));
    } else if (i < N1 + N2) {
        int q = i - N1;
        int j = q / HID, k = q % HID;
        float v;
        if (j < RELCOLS) v = W2[(((size_t)(j >> 6)) * HID + k) * HID + (j & 63)];
        else             v = root2[(size_t)k * HID + (j - RELCOLS)];
        __half hi = __float2half_rn(v);
        g_Wh2[q] = hi;
        g_Wl2[q] = __float2half_rn(v - __half2float(hi));
    }
}

// ---------------- mma.sync GEMM ----------------------------------------------
__device__ __forceinline__ uint32_t smem_u32(const void* p) {
    uint32_t a;
    asm("{ .reg .u64 t; cvta.to.shared.u64 t, %1; cvt.u32.u64 %0, t; }" : "=r"(a) : "l"(p));
    return a;
}
__device__ __forceinline__ void ldm4(uint32_t* r, uint32_t addr) {
    asm volatile("ldmatrix.sync.aligned.m8n8.x4.shared.b16 {%0,%1,%2,%3}, [%4];"
                 : "=r"(r[0]), "=r"(r[1]), "=r"(r[2]), "=r"(r[3]) : "r"(addr));
}
__device__ __forceinline__ void mma16816(float* d, const uint32_t* a, uint32_t b0, uint32_t b1) {
    asm volatile(
        "mma.sync.aligned.m16n8k16.row.col.f32.f16.f16.f32 "
        "{%0,%1,%2,%3}, {%4,%5,%6,%7}, {%8,%9}, {%0,%1,%2,%3};"
        : "+f"(d[0]), "+f"(d[1]), "+f"(d[2]), "+f"(d[3])
        : "r"(a[0]), "r"(a[1]), "r"(a[2]), "r"(a[3]), "r"(b0), "r"(b1));
}
__device__ __forceinline__ void cpa16(uint32_t saddr, const void* g) {
    asm volatile("cp.async.cg.shared.global [%0], [%1], 16;" :: "r"(saddr), "l"(g));
}
#define CP_COMMIT() asm volatile("cp.async.commit_group;" ::: "memory")
#define CP_WAIT0()  asm volatile("cp.async.wait_group 0;" ::: "memory")

__global__ void __launch_bounds__(256, 2) k_gemm_mma(const float* __restrict__ Xext,
                                                     int K, int useH,
                                                     const __half* __restrict__ Wh,
                                                     const __half* __restrict__ Wl) {
    extern __shared__ char smem[];
    const float* __restrict__ X = useH ? (const float*)g_h : Xext;
    const int RB = K * 2;
    const int OFF_A = 0;
    const int OFF_B0 = 128 * RB;
    uint32_t sb = smem_u32(smem);

    int tid = threadIdx.x, wid = tid >> 5, lane = tid & 31;
    int row0 = blockIdx.x * 128;
    int KQ = K >> 2;
    int CPR = K >> 3;

    auto prefetch = [&](int nb, int buf) {
        int bh = OFF_B0 + (buf * 2 + 0) * 64 * RB;
        int bl = OFF_B0 + (buf * 2 + 1) * 64 * RB;
        int col0 = nb * 64;
        for (int q = tid; q < 64 * CPR; q += 256) {
            int n = q / CPR, kc = q % CPR;
            size_t gsrc = (size_t)(col0 + n) * K + kc * 8;
            int off = n * RB + ((kc ^ (n & 7)) * 16);
            cpa16(sb + bh + off, Wh + gsrc);
            cpa16(sb + bl + off, Wl + gsrc);
        }
        CP_COMMIT();
    };

    prefetch(0, 0);

    for (int q = tid; q < 128 * KQ; q += 256) {
        int row = q / KQ, k = (q % KQ) * 4;
        float4 v = make_float4(0.f, 0.f, 0.f, 0.f);
        int rg = row0 + row;
        if (rg < NNODES) v = *(const float4*)(X + (size_t)rg * K + k);
        uint2 hp;
        __half2 p0 = __floats2half2_rn(v.x, v.y);
        __half2 p1 = __floats2half2_rn(v.z, v.w);
        hp.x = *(uint32_t*)&p0;
        hp.y = *(uint32_t*)&p1;
        int chunk = (k >> 3) ^ (row & 7);
        *(uint2*)(smem + OFF_A + row * RB + chunk * 16 + (k & 7) * 2) = hp;
    }
    CP_WAIT0();
    __syncthreads();

    int wrow = (wid >> 1) * 32;
    int wcol = (wid & 1) * 32;

    int arow[2], as[2];
#pragma unroll
    for (int mt = 0; mt < 2; mt++) {
        int r = wrow + mt * 16 + (lane & 7) + ((lane >> 3) & 1) * 8;
        arow[mt] = r * RB;
        as[mt] = r & 7;
    }
    int akc = lane >> 4;
    int brow[2], bs[2];
#pragma unroll
    for (int nt2 = 0; nt2 < 2; nt2++) {
        int n = wcol + nt2 * 16 + (lane & 7) + (lane >> 4) * 8;
        brow[nt2] = n * RB;
        bs[nt2] = n & 7;
    }
    int bkc = (lane >> 3) & 1;
    int nkstep = K >> 4;

    for (int nb = 0; nb < 9; nb++) {
        int cur = nb & 1;
        if (nb < 8) prefetch(nb + 1, cur ^ 1);

        uint32_t bhB = sb + OFF_B0 + (cur * 2 + 0) * 64 * RB;
        uint32_t blB = sb + OFF_B0 + (cur * 2 + 1) * 64 * RB;

        float acc[2][4][4];
#pragma unroll
        for (int mt = 0; mt < 2; mt++)
#pragma unroll
            for (int nt = 0; nt < 4; nt++)
#pragma unroll
                for (int j = 0; j < 4; j++) acc[mt][nt][j] = 0.f;

        for (int ks = 0; ks < nkstep; ks++) {
            int kc0 = ks * 2;
            uint32_t ah[2][4], bh[2][4], bl[2][4];
#pragma unroll
            for (int mt = 0; mt < 2; mt++) {
                uint32_t off = arow[mt] + (uint32_t)(((kc0 + akc) ^ as[mt]) * 16);
                ldm4(ah[mt], sb + OFF_A + off);
            }
#pragma unroll
            for (int nt2 = 0; nt2 < 2; nt2++) {
                uint32_t off = brow[nt2] + (uint32_t)(((kc0 + bkc) ^ bs[nt2]) * 16);
                ldm4(bh[nt2], bhB + off);
                ldm4(bl[nt2], blB + off);
            }
#pragma unroll
            for (int mt = 0; mt < 2; mt++) {
#pragma unroll
                for (int nt = 0; nt < 4; nt++) {
                    uint32_t h0 = bh[nt >> 1][(nt & 1) * 2], h1 = bh[nt >> 1][(nt & 1) * 2 + 1];
                    uint32_t l0 = bl[nt >> 1][(nt & 1) * 2], l1 = bl[nt >> 1][(nt & 1) * 2 + 1];
                    mma16816(acc[mt][nt], ah[mt], h0, h1);
                    mma16816(acc[mt][nt], ah[mt], l0, l1);
                }
            }
        }

        int col0 = nb * 64;
        if (nb < 8) {
#pragma unroll
            for (int mt = 0; mt < 2; mt++) {
                int r0 = row0 + wrow + mt * 16 + (lane >> 2);
#pragma unroll
                for (int nt = 0; nt < 4; nt++) {
                    int c = col0 + wcol + nt * 8 + (lane & 3) * 2;
                    if (r0 < NNODES)
                        *(__half2*)(g_Ym + (size_t)r0 * RELCOLS + c) =
                            __floats2half2_rn(acc[mt][nt][0], acc[mt][nt][1]);
                    if (r0 + 8 < NNODES)
                        *(__half2*)(g_Ym + (size_t)(r0 + 8) * RELCOLS + c) =
                            __floats2half2_rn(acc[mt][nt][2], acc[mt][nt][3]);
                }
            }
        } else {
#pragma unroll
            for (int mt = 0; mt < 2; mt++) {
                int r0 = row0 + wrow + mt * 16 + (lane >> 2);
#pragma unroll
                for (int nt = 0; nt < 4; nt++) {
                    int c = wcol + nt * 8 + (lane & 3) * 2;
                    if (r0 < NNODES)
                        *(float2*)(g_Yroot + (size_t)r0 * HID + c) =
                            make_float2(acc[mt][nt][0], acc[mt][nt][1]);
                    if (r0 + 8 < NNODES)
                        *(float2*)(g_Yroot + (size_t)(r0 + 8) * HID + c) =
                            make_float2(acc[mt][nt][2], acc[mt][nt][3]);
                }
            }
        }
        if (nb < 8) {
            CP_WAIT0();
            __syncthreads();
        }
    }
}

// ---------------- aggregation: warp per node, 8 edges per warp-load ----------
// lane = (grp = lane>>2, sub = lane&3); lane loads 32B (16 halves) of edge e+grp
// via 256-bit evict_last load. Cross-grp combine: shfl_xor 4/8/16.
__device__ __forceinline__ void ldg_el32(uint32_t* r, const void* p) {
    asm volatile("ld.global.nc.L2::evict_last.v8.b32 {%0,%1,%2,%3,%4,%5,%6,%7}, [%8];"
                 : "=r"(r[0]), "=r"(r[1]), "=r"(r[2]), "=r"(r[3]),
                   "=r"(r[4]), "=r"(r[5]), "=r"(r[6]), "=r"(r[7]) : "l"(p));
}

__global__ void __launch_bounds__(256) k_agg(const float* __restrict__ bias,
                                             float* __restrict__ outext, int mode) {
    int warp = (blockIdx.x * blockDim.x + threadIdx.x) >> 5;
    int lane = threadIdx.x & 31;
    if (warp >= NNODES) return;
    float* __restrict__ out = mode ? (float*)g_h : outext;

    int grp = lane >> 2;      // 0..7: edge slot
    int sub = lane & 3;       // 0..3: 16-half channel slice
    int start = g_rowptr[warp];
    int end   = g_rowptr[warp + 1];

    float acc[16];
#pragma unroll
    for (int j = 0; j < 16; j++) acc[j] = 0.f;

    int e = start;
    // main loop: 16 edges per iteration (two 8-edge rounds in flight)
    for (; e + 16 <= end; e += 16) {
        int2 m0 = __ldcs(&g_emeta[e + grp]);
        int2 m1 = __ldcs(&g_emeta[e + 8 + grp]);
        uint32_t r0[8], r1[8];
        ldg_el32(r0, g_Ym + m0.x + sub * 16);
        ldg_el32(r1, g_Ym + m1.x + sub * 16);
        float s0 = __int_as_float(m0.y);
        float s1 = __int_as_float(m1.y);
#pragma unroll
        for (int j = 0; j < 8; j++) {
            float2 f0 = __half22float2(*(const __half2*)&r0[j]);
            float2 f1 = __half22float2(*(const __half2*)&r1[j]);
            acc[j * 2 + 0] = fmaf(f0.x, s0, acc[j * 2 + 0]);
            acc[j * 2 + 1] = fmaf(f0.y, s0, acc[j * 2 + 1]);
            acc[j * 2 + 0] = fmaf(f1.x, s1, acc[j * 2 + 0]);
            acc[j * 2 + 1] = fmaf(f1.y, s1, acc[j * 2 + 1]);
        }
    }
    // tail: predicated 8-edge rounds
    for (; e < end; e += 8) {
        int ei = e + grp;
        int ec = ei < end ? ei : e;
        int2 m = __ldcs(&g_emeta[ec]);
        float s = (ei < end) ? __int_as_float(m.y) : 0.f;
        uint32_t r[8];
        ldg_el32(r, g_Ym + m.x + sub * 16);
#pragma unroll
        for (int j = 0; j < 8; j++) {
            float2 f = __half22float2(*(const __half2*)&r[j]);
            acc[j * 2 + 0] = fmaf(f.x, s, acc[j * 2 + 0]);
            acc[j * 2 + 1] = fmaf(f.y, s, acc[j * 2 + 1]);
        }
    }

    // combine the 8 edge-groups (lanes with equal sub differ by multiples of 4)
#pragma unroll
    for (int j = 0; j < 16; j++) {
        acc[j] += __shfl_xor_sync(0xFFFFFFFFu, acc[j], 4);
        acc[j] += __shfl_xor_sync(0xFFFFFFFFu, acc[j], 8);
        acc[j] += __shfl_xor_sync(0xFFFFFFFFu, acc[j], 16);
    }

    if (grp == 0) {
        const float* rootp = g_Yroot + (size_t)warp * HID + sub * 16;
        const float* biasp = bias + sub * 16;
        float* op = out + (size_t)warp * HID + sub * 16;
#pragma unroll
        for (int q = 0; q < 4; q++) {
            float4 rv = *(const float4*)(rootp + q * 4);
            float4 bv = *(const float4*)(biasp + q * 4);
            float4 o;
            o.x = acc[q * 4 + 0] + rv.x + bv.x;
            o.y = acc[q * 4 + 1] + rv.y + bv.y;
            o.z = acc[q * 4 + 2] + rv.z + bv.z;
            o.w = acc[q * 4 + 3] + rv.w + bv.w;
            if (mode) {
                o.x = fmaxf(o.x, 0.f); o.y = fmaxf(o.y, 0.f);
                o.z = fmaxf(o.z, 0.f); o.w = fmaxf(o.w, 0.f);
            }
            *(float4*)(op + q * 4) = o;
        }
    }
}

// ---------------- launch ------------------------------------------------------
extern "C" void kernel_launch(void* const* d_in, const int* in_sizes, int n_in,
                              void* d_out, int out_size) {
    const float* x     = (const float*)d_in[0];
    const int*   ei    = (const int*)d_in[1];
    const int*   et    = (const int*)d_in[2];
    const float* W1    = (const float*)d_in[3];
    const float* root1 = (const float*)d_in[4];
    const float* b1    = (const float*)d_in[5];
    const float* W2    = (const float*)d_in[6];
    const float* root2 = (const float*)d_in[7];
    const float* b2    = (const float*)d_in[8];
    float* out = (float*)d_out;

    const int* src = ei;
    const int* dst = ei + NEDGES;

    static cudaStream_t s1 = nullptr, s2 = nullptr;
    static cudaEvent_t ev_fork = nullptr, ev_csr = nullptr, ev_pack = nullptr;
    static void* cnt_ptr = nullptr;
    static const __half *wh1p, *wl1p, *wh2p, *wl2p;
    if (!s1) {
        cudaStreamCreateWithFlags(&s1, cudaStreamNonBlocking);
        cudaStreamCreateWithFlags(&s2, cudaStreamNonBlocking);
        cudaEventCreateWithFlags(&ev_fork, cudaEventDisableTiming);
        cudaEventCreateWithFlags(&ev_csr, cudaEventDisableTiming);
        cudaEventCreateWithFlags(&ev_pack, cudaEventDisableTiming);
        cudaGetSymbolAddress(&cnt_ptr, g_cnt);
        void* p;
        cudaGetSymbolAddress(&p, g_Wh1); wh1p = (const __half*)p;
        cudaGetSymbolAddress(&p, g_Wl1); wl1p = (const __half*)p;
        cudaGetSymbolAddress(&p, g_Wh2); wh2p = (const __half*)p;
        cudaGetSymbolAddress(&p, g_Wl2); wl2p = (const __half*)p;
        cudaFuncSetAttribute(k_gemm_mma, cudaFuncAttributeMaxDynamicSharedMemorySize,
                             384 * CIN * 2);
    }

    // ---- fork: CSR build on s1, weight packs on s2 ----
    cudaEventRecord(ev_fork, 0);
    cudaStreamWaitEvent(s1, ev_fork, 0);
    cudaStreamWaitEvent(s2, ev_fork, 0);

    cudaMemsetAsync(cnt_ptr, 0, sizeof(int) * NREL * NNODES, s1);
    k_count<<<(NEDGES + 255) / 256, 256, 0, s1>>>(dst, et);
    int nb = (NNODES + 1023) / 1024;
    k_scan1<<<nb, 1024, 0, s1>>>();
    k_scan2<<<1, 32, 0, s1>>>(nb);
    k_scan3<<<(NNODES + 255) / 256, 256, 0, s1>>>();
    k_scatter<<<(NEDGES + 255) / 256, 256, 0, s1>>>(src, dst, et);
    cudaEventRecord(ev_csr, s1);

    int npack = YCOLS * CIN + YCOLS * HID;
    k_pack_all<<<(npack + 255) / 256, 256, 0, s2>>>(W1, root1, W2, root2);
    cudaEventRecord(ev_pack, s2);

    int ggrid = (NNODES + 127) / 128;
    int agrid = (NNODES * 32 + 255) / 256;

    // main stream: gemm1 needs packed weights only
    cudaStreamWaitEvent(0, ev_pack, 0);
    k_gemm_mma<<<ggrid, 256, 384 * CIN * 2>>>(x, CIN, 0, wh1p, wl1p);

    // join CSR before agg1
    cudaStreamWaitEvent(0, ev_csr, 0);
    k_agg<<<agrid, 256>>>(b1, nullptr, 1);

    // layer 2 (weights already packed)
    k_gemm_mma<<<ggrid, 256, 384 * HID * 2>>>(nullptr, HID, 1, wh2p, wl2p);
    k_agg<<<agrid, 256>>>(b2, out, 0);
}

// round 13
// speedup vs baseline: 1.1081x; 1.1081x over previous
#include <cuda_runtime.h>
#include <cuda_fp16.h>
#include <cstdint>

#define NNODES 100000
#define NEDGES 3200000
#define NREL   8
#define CIN    128
#define HID    64
#define RELCOLS 512
#define YCOLS (RELCOLS + HID)

// ---------------- scratch ----------------------------------------------------
__device__ __align__(16) __half g_Ym[(size_t)NNODES * RELCOLS];   // relation msgs fp16
__device__ __align__(16) float  g_Yroot[(size_t)NNODES * HID];    // root part fp32
__device__ __align__(16) float  g_h[(size_t)NNODES * HID];
__device__ __align__(16) __half g_Wh1[YCOLS * CIN];
__device__ __align__(16) __half g_Wl1[YCOLS * CIN];
__device__ __align__(16) __half g_Wh2[YCOLS * HID];
__device__ __align__(16) __half g_Wl2[YCOLS * HID];
__device__ int   g_cnt[NREL * NNODES];
__device__ int   g_rowptr[NNODES + 1];
__device__ int   g_cursor[NNODES];
__device__ int   g_bsums[256];
__device__ int2  g_emeta[NEDGES];

// ---------------- CSR build --------------------------------------------------
__global__ void k_count(const int* __restrict__ dst, const int* __restrict__ et) {
    int e = blockIdx.x * blockDim.x + threadIdx.x;
    if (e < NEDGES) atomicAdd(&g_cnt[__ldcs(et + e) * NNODES + __ldcs(dst + e)], 1);
}
__global__ void k_scan1() {
    __shared__ int sh[1024];
    int d = blockIdx.x * 1024 + threadIdx.x;
    int tot = 0;
    if (d < NNODES) {
#pragma unroll
        for (int r = 0; r < NREL; r++) tot += g_cnt[r * NNODES + d];
    }
    sh[threadIdx.x] = tot;
    __syncthreads();
    for (int off = 1; off < 1024; off <<= 1) {
        int v = 0;
        if (threadIdx.x >= off) v = sh[threadIdx.x - off];
        __syncthreads();
        sh[threadIdx.x] += v;
        __syncthreads();
    }
    if (d < NNODES) g_rowptr[d] = sh[threadIdx.x] - tot;
    if (threadIdx.x == 1023) g_bsums[blockIdx.x] = sh[1023];
}
__global__ void k_scan2(int nb) {
    if (threadIdx.x == 0 && blockIdx.x == 0) {
        int run = 0;
        for (int i = 0; i < nb; i++) { int v = g_bsums[i]; g_bsums[i] = run; run += v; }
    }
}
__global__ void k_scan3() {
    int d = blockIdx.x * blockDim.x + threadIdx.x;
    if (d < NNODES) {
        int v = g_rowptr[d] + g_bsums[d >> 10];
        g_rowptr[d] = v;
        g_cursor[d] = v;
    }
    if (d == 0) g_rowptr[NNODES] = NEDGES;
}
__global__ void k_scatter(const int* __restrict__ src, const int* __restrict__ dst,
                          const int* __restrict__ et) {
    int e = blockIdx.x * blockDim.x + threadIdx.x;
    if (e >= NEDGES) return;
    int s = __ldcs(src + e), d = __ldcs(dst + e), r = __ldcs(et + e);
    int pos = atomicAdd(&g_cursor[d], 1);
    float sc = 1.0f / (float)g_cnt[r * NNODES + d];
    g_emeta[pos] = make_int2(s * RELCOLS + r * HID, __float_as_int(sc));
}

// ---------------- merged weight pack (both layers) ----------------------------
__global__ void k_pack_all(const float* __restrict__ W1, const float* __restrict__ root1,
                           const float* __restrict__ W2, const float* __restrict__ root2) {
    int i = blockIdx.x * blockDim.x + threadIdx.x;
    const int N1 = YCOLS * CIN;
    const int N2 = YCOLS * HID;
    if (i < N1) {
        int j = i / CIN, k = i % CIN;
        float v;
        if (j < RELCOLS) v = W1[(((size_t)(j >> 6)) * CIN + k) * HID + (j & 63)];
        else             v = root1[(size_t)k * HID + (j - RELCOLS)];
        __half hi = __float2half_rn(v);
        g_Wh1[i] = hi;
        g_Wl1[i] = __float2half_rn(v - __half2float(hi));
    } else if (i < N1 + N2) {
        int q = i - N1;
        int j = q / HID, k = q % HID;
        float v;
        if (j < RELCOLS) v = W2[(((size_t)(j >> 6)) * HID + k) * HID + (j & 63)];
        else             v = root2[(size_t)k * HID + (j - RELCOLS)];
        __half hi = __float2half_rn(v);
        g_Wh2[q] = hi;
        g_Wl2[q] = __float2half_rn(v - __half2float(hi));
    }
}

// ---------------- mma.sync GEMM ----------------------------------------------
__device__ __forceinline__ uint32_t smem_u32(const void* p) {
    uint32_t a;
    asm("{ .reg .u64 t; cvta.to.shared.u64 t, %1; cvt.u32.u64 %0, t; }" : "=r"(a) : "l"(p));
    return a;
}
__device__ __forceinline__ void ldm4(uint32_t* r, uint32_t addr) {
    asm volatile("ldmatrix.sync.aligned.m8n8.x4.shared.b16 {%0,%1,%2,%3}, [%4];"
                 : "=r"(r[0]), "=r"(r[1]), "=r"(r[2]), "=r"(r[3]) : "r"(addr));
}
__device__ __forceinline__ void mma16816(float* d, const uint32_t* a, uint32_t b0, uint32_t b1) {
    asm volatile(
        "mma.sync.aligned.m16n8k16.row.col.f32.f16.f16.f32 "
        "{%0,%1,%2,%3}, {%4,%5,%6,%7}, {%8,%9}, {%0,%1,%2,%3};"
        : "+f"(d[0]), "+f"(d[1]), "+f"(d[2]), "+f"(d[3])
        : "r"(a[0]), "r"(a[1]), "r"(a[2]), "r"(a[3]), "r"(b0), "r"(b1));
}
__device__ __forceinline__ void cpa16(uint32_t saddr, const void* g) {
    asm volatile("cp.async.cg.shared.global [%0], [%1], 16;" :: "r"(saddr), "l"(g));
}
#define CP_COMMIT() asm volatile("cp.async.commit_group;" ::: "memory")
#define CP_WAIT0()  asm volatile("cp.async.wait_group 0;" ::: "memory")

__global__ void __launch_bounds__(256, 2) k_gemm_mma(const float* __restrict__ Xext,
                                                     int K, int useH,
                                                     const __half* __restrict__ Wh,
                                                     const __half* __restrict__ Wl) {
    extern __shared__ char smem[];
    const float* __restrict__ X = useH ? (const float*)g_h : Xext;
    const int RB = K * 2;
    const int OFF_A = 0;
    const int OFF_B0 = 128 * RB;
    uint32_t sb = smem_u32(smem);

    int tid = threadIdx.x, wid = tid >> 5, lane = tid & 31;
    int row0 = blockIdx.x * 128;
    int KQ = K >> 2;
    int CPR = K >> 3;

    auto prefetch = [&](int nb, int buf) {
        int bh = OFF_B0 + (buf * 2 + 0) * 64 * RB;
        int bl = OFF_B0 + (buf * 2 + 1) * 64 * RB;
        int col0 = nb * 64;
        for (int q = tid; q < 64 * CPR; q += 256) {
            int n = q / CPR, kc = q % CPR;
            size_t gsrc = (size_t)(col0 + n) * K + kc * 8;
            int off = n * RB + ((kc ^ (n & 7)) * 16);
            cpa16(sb + bh + off, Wh + gsrc);
            cpa16(sb + bl + off, Wl + gsrc);
        }
        CP_COMMIT();
    };

    prefetch(0, 0);

    for (int q = tid; q < 128 * KQ; q += 256) {
        int row = q / KQ, k = (q % KQ) * 4;
        float4 v = make_float4(0.f, 0.f, 0.f, 0.f);
        int rg = row0 + row;
        if (rg < NNODES) v = *(const float4*)(X + (size_t)rg * K + k);
        uint2 hp;
        __half2 p0 = __floats2half2_rn(v.x, v.y);
        __half2 p1 = __floats2half2_rn(v.z, v.w);
        hp.x = *(uint32_t*)&p0;
        hp.y = *(uint32_t*)&p1;
        int chunk = (k >> 3) ^ (row & 7);
        *(uint2*)(smem + OFF_A + row * RB + chunk * 16 + (k & 7) * 2) = hp;
    }
    CP_WAIT0();
    __syncthreads();

    int wrow = (wid >> 1) * 32;
    int wcol = (wid & 1) * 32;

    int arow[2], as[2];
#pragma unroll
    for (int mt = 0; mt < 2; mt++) {
        int r = wrow + mt * 16 + (lane & 7) + ((lane >> 3) & 1) * 8;
        arow[mt] = r * RB;
        as[mt] = r & 7;
    }
    int akc = lane >> 4;
    int brow[2], bs[2];
#pragma unroll
    for (int nt2 = 0; nt2 < 2; nt2++) {
        int n = wcol + nt2 * 16 + (lane & 7) + (lane >> 4) * 8;
        brow[nt2] = n * RB;
        bs[nt2] = n & 7;
    }
    int bkc = (lane >> 3) & 1;
    int nkstep = K >> 4;

    for (int nb = 0; nb < 9; nb++) {
        int cur = nb & 1;
        if (nb < 8) prefetch(nb + 1, cur ^ 1);

        uint32_t bhB = sb + OFF_B0 + (cur * 2 + 0) * 64 * RB;
        uint32_t blB = sb + OFF_B0 + (cur * 2 + 1) * 64 * RB;

        float acc[2][4][4];
#pragma unroll
        for (int mt = 0; mt < 2; mt++)
#pragma unroll
            for (int nt = 0; nt < 4; nt++)
#pragma unroll
                for (int j = 0; j < 4; j++) acc[mt][nt][j] = 0.f;

        for (int ks = 0; ks < nkstep; ks++) {
            int kc0 = ks * 2;
            uint32_t ah[2][4], bh[2][4], bl[2][4];
#pragma unroll
            for (int mt = 0; mt < 2; mt++) {
                uint32_t off = arow[mt] + (uint32_t)(((kc0 + akc) ^ as[mt]) * 16);
                ldm4(ah[mt], sb + OFF_A + off);
            }
#pragma unroll
            for (int nt2 = 0; nt2 < 2; nt2++) {
                uint32_t off = brow[nt2] + (uint32_t)(((kc0 + bkc) ^ bs[nt2]) * 16);
                ldm4(bh[nt2], bhB + off);
                ldm4(bl[nt2], blB + off);
            }
#pragma unroll
            for (int mt = 0; mt < 2; mt++) {
#pragma unroll
                for (int nt = 0; nt < 4; nt++) {
                    uint32_t h0 = bh[nt >> 1][(nt & 1) * 2], h1 = bh[nt >> 1][(nt & 1) * 2 + 1];
                    uint32_t l0 = bl[nt >> 1][(nt & 1) * 2], l1 = bl[nt >> 1][(nt & 1) * 2 + 1];
                    mma16816(acc[mt][nt], ah[mt], h0, h1);
                    mma16816(acc[mt][nt], ah[mt], l0, l1);
                }
            }
        }

        int col0 = nb * 64;
        if (nb < 8) {
#pragma unroll
            for (int mt = 0; mt < 2; mt++) {
                int r0 = row0 + wrow + mt * 16 + (lane >> 2);
#pragma unroll
                for (int nt = 0; nt < 4; nt++) {
                    int c = col0 + wcol + nt * 8 + (lane & 3) * 2;
                    if (r0 < NNODES)
                        *(__half2*)(g_Ym + (size_t)r0 * RELCOLS + c) =
                            __floats2half2_rn(acc[mt][nt][0], acc[mt][nt][1]);
                    if (r0 + 8 < NNODES)
                        *(__half2*)(g_Ym + (size_t)(r0 + 8) * RELCOLS + c) =
                            __floats2half2_rn(acc[mt][nt][2], acc[mt][nt][3]);
                }
            }
        } else {
#pragma unroll
            for (int mt = 0; mt < 2; mt++) {
                int r0 = row0 + wrow + mt * 16 + (lane >> 2);
#pragma unroll
                for (int nt = 0; nt < 4; nt++) {
                    int c = wcol + nt * 8 + (lane & 3) * 2;
                    if (r0 < NNODES)
                        *(float2*)(g_Yroot + (size_t)r0 * HID + c) =
                            make_float2(acc[mt][nt][0], acc[mt][nt][1]);
                    if (r0 + 8 < NNODES)
                        *(float2*)(g_Yroot + (size_t)(r0 + 8) * HID + c) =
                            make_float2(acc[mt][nt][2], acc[mt][nt][3]);
                }
            }
        }
        if (nb < 8) {
            CP_WAIT0();
            __syncthreads();
        }
    }
}

// ---------------- aggregation: warp per node, 4 edges per warp-load ----------
// (R7-proven version: uint4 loads, default caching, 8 accumulators)
__global__ void __launch_bounds__(256) k_agg(const float* __restrict__ bias,
                                             float* __restrict__ outext, int mode) {
    int warp = (blockIdx.x * blockDim.x + threadIdx.x) >> 5;
    int lane = threadIdx.x & 31;
    if (warp >= NNODES) return;
    float* __restrict__ out = mode ? (float*)g_h : outext;

    int grp = lane >> 3;
    int sub = lane & 7;
    int start = g_rowptr[warp];
    int end   = g_rowptr[warp + 1];

    float acc[8];
#pragma unroll
    for (int j = 0; j < 8; j++) acc[j] = 0.f;

    int e = start;
    for (; e + 16 <= end; e += 16) {
        int2 m0 = __ldcs(&g_emeta[e + grp]);
        int2 m1 = __ldcs(&g_emeta[e + 4 + grp]);
        int2 m2 = __ldcs(&g_emeta[e + 8 + grp]);
        int2 m3 = __ldcs(&g_emeta[e + 12 + grp]);
        uint4 r0 = *(const uint4*)(g_Ym + m0.x + sub * 8);
        uint4 r1 = *(const uint4*)(g_Ym + m1.x + sub * 8);
        uint4 r2 = *(const uint4*)(g_Ym + m2.x + sub * 8);
        uint4 r3 = *(const uint4*)(g_Ym + m3.x + sub * 8);
        float s0 = __int_as_float(m0.y), s1 = __int_as_float(m1.y);
        float s2 = __int_as_float(m2.y), s3 = __int_as_float(m3.y);
        const __half2* h0 = (const __half2*)&r0;
        const __half2* h1 = (const __half2*)&r1;
        const __half2* h2 = (const __half2*)&r2;
        const __half2* h3 = (const __half2*)&r3;
#pragma unroll
        for (int j = 0; j < 4; j++) {
            float2 f0 = __half22float2(h0[j]);
            float2 f1 = __half22float2(h1[j]);
            float2 f2 = __half22float2(h2[j]);
            float2 f3 = __half22float2(h3[j]);
            acc[j * 2 + 0] = fmaf(f0.x, s0, acc[j * 2 + 0]);
            acc[j * 2 + 1] = fmaf(f0.y, s0, acc[j * 2 + 1]);
            acc[j * 2 + 0] = fmaf(f1.x, s1, acc[j * 2 + 0]);
            acc[j * 2 + 1] = fmaf(f1.y, s1, acc[j * 2 + 1]);
            acc[j * 2 + 0] = fmaf(f2.x, s2, acc[j * 2 + 0]);
            acc[j * 2 + 1] = fmaf(f2.y, s2, acc[j * 2 + 1]);
            acc[j * 2 + 0] = fmaf(f3.x, s3, acc[j * 2 + 0]);
            acc[j * 2 + 1] = fmaf(f3.y, s3, acc[j * 2 + 1]);
        }
    }
    for (; e < end; e += 4) {
        int ei = e + grp;
        int ec = ei < end ? ei : e;
        int2 m = g_emeta[ec];
        float s = (ei < end) ? __int_as_float(m.y) : 0.f;
        uint4 r = *(const uint4*)(g_Ym + m.x + sub * 8);
        const __half2* h = (const __half2*)&r;
#pragma unroll
        for (int j = 0; j < 4; j++) {
            float2 f = __half22float2(h[j]);
            acc[j * 2 + 0] = fmaf(f.x, s, acc[j * 2 + 0]);
            acc[j * 2 + 1] = fmaf(f.y, s, acc[j * 2 + 1]);
        }
    }

#pragma unroll
    for (int j = 0; j < 8; j++) {
        acc[j] += __shfl_xor_sync(0xFFFFFFFFu, acc[j], 8);
        acc[j] += __shfl_xor_sync(0xFFFFFFFFu, acc[j], 16);
    }

    if (grp == 0) {
        const float* rootp = g_Yroot + (size_t)warp * HID + sub * 8;
        float4 rv0 = *(const float4*)(rootp + 0);
        float4 rv1 = *(const float4*)(rootp + 4);
        float4 bv0 = *(const float4*)(bias + sub * 8 + 0);
        float4 bv1 = *(const float4*)(bias + sub * 8 + 4);
        float4 o0, o1;
        o0.x = acc[0] + rv0.x + bv0.x; o0.y = acc[1] + rv0.y + bv0.y;
        o0.z = acc[2] + rv0.z + bv0.z; o0.w = acc[3] + rv0.w + bv0.w;
        o1.x = acc[4] + rv1.x + bv1.x; o1.y = acc[5] + rv1.y + bv1.y;
        o1.z = acc[6] + rv1.z + bv1.z; o1.w = acc[7] + rv1.w + bv1.w;
        if (mode) {
            o0.x = fmaxf(o0.x, 0.f); o0.y = fmaxf(o0.y, 0.f);
            o0.z = fmaxf(o0.z, 0.f); o0.w = fmaxf(o0.w, 0.f);
            o1.x = fmaxf(o1.x, 0.f); o1.y = fmaxf(o1.y, 0.f);
            o1.z = fmaxf(o1.z, 0.f); o1.w = fmaxf(o1.w, 0.f);
        }
        float* op = out + (size_t)warp * HID + sub * 8;
        *(float4*)(op + 0) = o0;
        *(float4*)(op + 4) = o1;
    }
}

// ---------------- launch ------------------------------------------------------
extern "C" void kernel_launch(void* const* d_in, const int* in_sizes, int n_in,
                              void* d_out, int out_size) {
    const float* x     = (const float*)d_in[0];
    const int*   ei    = (const int*)d_in[1];
    const int*   et    = (const int*)d_in[2];
    const float* W1    = (const float*)d_in[3];
    const float* root1 = (const float*)d_in[4];
    const float* b1    = (const float*)d_in[5];
    const float* W2    = (const float*)d_in[6];
    const float* root2 = (const float*)d_in[7];
    const float* b2    = (const float*)d_in[8];
    float* out = (float*)d_out;

    const int* src = ei;
    const int* dst = ei + NEDGES;

    static cudaStream_t s1 = nullptr, s2 = nullptr;
    static cudaEvent_t ev_fork = nullptr, ev_csr = nullptr, ev_pack = nullptr;
    static void* cnt_ptr = nullptr;
    static const __half *wh1p, *wl1p, *wh2p, *wl2p;
    if (!s1) {
        cudaStreamCreateWithFlags(&s1, cudaStreamNonBlocking);
        cudaStreamCreateWithFlags(&s2, cudaStreamNonBlocking);
        cudaEventCreateWithFlags(&ev_fork, cudaEventDisableTiming);
        cudaEventCreateWithFlags(&ev_csr, cudaEventDisableTiming);
        cudaEventCreateWithFlags(&ev_pack, cudaEventDisableTiming);
        cudaGetSymbolAddress(&cnt_ptr, g_cnt);
        void* p;
        cudaGetSymbolAddress(&p, g_Wh1); wh1p = (const __half*)p;
        cudaGetSymbolAddress(&p, g_Wl1); wl1p = (const __half*)p;
        cudaGetSymbolAddress(&p, g_Wh2); wh2p = (const __half*)p;
        cudaGetSymbolAddress(&p, g_Wl2); wl2p = (const __half*)p;
        cudaFuncSetAttribute(k_gemm_mma, cudaFuncAttributeMaxDynamicSharedMemorySize,
                             384 * CIN * 2);
    }

    // ---- fork: CSR build on s1, weight packs on s2 ----
    cudaEventRecord(ev_fork, 0);
    cudaStreamWaitEvent(s1, ev_fork, 0);
    cudaStreamWaitEvent(s2, ev_fork, 0);

    cudaMemsetAsync(cnt_ptr, 0, sizeof(int) * NREL * NNODES, s1);
    k_count<<<(NEDGES + 255) / 256, 256, 0, s1>>>(dst, et);
    int nb = (NNODES + 1023) / 1024;
    k_scan1<<<nb, 1024, 0, s1>>>();
    k_scan2<<<1, 32, 0, s1>>>(nb);
    k_scan3<<<(NNODES + 255) / 256, 256, 0, s1>>>();
    k_scatter<<<(NEDGES + 255) / 256, 256, 0, s1>>>(src, dst, et);
    cudaEventRecord(ev_csr, s1);

    int npack = YCOLS * CIN + YCOLS * HID;
    k_pack_all<<<(npack + 255) / 256, 256, 0, s2>>>(W1, root1, W2, root2);
    cudaEventRecord(ev_pack, s2);

    int ggrid = (NNODES + 127) / 128;
    int agrid = (NNODES * 32 + 255) / 256;

    // main stream: gemm1 needs packed weights only
    cudaStreamWaitEvent(0, ev_pack, 0);
    k_gemm_mma<<<ggrid, 256, 384 * CIN * 2>>>(x, CIN, 0, wh1p, wl1p);

    // join CSR before agg1
    cudaStreamWaitEvent(0, ev_csr, 0);
    k_agg<<<agrid, 256>>>(b1, nullptr, 1);

    // layer 2 (weights already packed)
    k_gemm_mma<<<ggrid, 256, 384 * HID * 2>>>(nullptr, HID, 1, wh2p, wl2p);
    k_agg<<<agrid, 256>>>(b2, out, 0);
}